// round 10
// baseline (speedup 1.0000x reference)
#include <cuda_runtime.h>
#include <cstdint>

// Gate_60421599920823 : MoE sigmoid gating (fp32 FFMA2 path; tcgen05 unavailable —
// harness ptxas targets sm_103 without the 'a' suffix).
//   logits = x[8192,4096] @ W^T[4096,64] (fp32)
//   scores = sigmoid(logits); top-2 on (scores + bias); weights normalized.
// Output: [weights N*2 | indices-as-float N*2 | scores N*64]

#define D_DIM    4096
#define NEXP     64
#define TILE_M   64
#define KC       64
#define NC       (D_DIM / KC)      // 64
#define THREADS  512
#define NBUF     3
#define XPITCH   68

#define X_STAGE_BYTES  (TILE_M * XPITCH * 4)        // 17408
#define W_STAGE_BYTES  (NEXP * KC * 4)              // 16384
#define X_OFF(b)       ((b) * X_STAGE_BYTES)
#define W_OFF(b)       (NBUF * X_STAGE_BYTES + (b) * W_STAGE_BYTES)
#define SMEM_TOTAL     (NBUF * (X_STAGE_BYTES + W_STAGE_BYTES))   // 101376
#define C_STRIDE       68

typedef unsigned long long ull;

__device__ __forceinline__ void ffma2(ull& d, ull a, ull b) {
    asm("fma.rn.f32x2 %0, %1, %2, %3;" : "=l"(d) : "l"(a), "l"(b), "l"(d));
}

__global__ __launch_bounds__(THREADS, 1)
void gate_kernel(const float* __restrict__ x,
                 const float* __restrict__ w,
                 const float* __restrict__ bias,
                 float* __restrict__ out_w,
                 float* __restrict__ out_i,
                 float* __restrict__ out_s)
{
    extern __shared__ char smem[];
    const int tid = threadIdx.x;
    const int row_base = blockIdx.x * TILE_M;

    // warp-level tiling: warp covers 8 rows x 32 experts
    const int l   = tid & 31;
    const int wid = tid >> 5;          // 0..15
    const int tx  = l & 7;             // expert lane: e = eh + 8j + tx
    const int ty  = l >> 3;            // 0..3
    const int eh  = (wid & 1) * 32;    // expert half
    const int rw  = (wid >> 1) * 8 + ty * 2;  // thread's first row in tile

    // ---- async chunk loader (2 X-float4 + 2 W-float4 per thread) ----------
    auto load_chunk = [&](int c, int buf) {
        const int k0 = c * KC;
        float* Xb = (float*)(smem + X_OFF(buf));
        float* Wb = (float*)(smem + W_OFF(buf));
        #pragma unroll
        for (int i = 0; i < 2; ++i) {                 // X: 64 rows x 16 float4
            int lin = tid + i * THREADS;              // 0..1023
            int r   = lin >> 4;
            int c4  = lin & 15;
            const float* src = x + (size_t)(row_base + r) * D_DIM + k0 + c4 * 4;
            uint32_t dst = (uint32_t)__cvta_generic_to_shared(&Xb[r * XPITCH + c4 * 4]);
            asm volatile("cp.async.cg.shared.global [%0], [%1], 16;\n" :: "r"(dst), "l"(src));
        }
        #pragma unroll
        for (int i = 0; i < 2; ++i) {                 // W: 64 rows x 16 float4, slot = c4 ^ (e&7)
            int lin = tid + i * THREADS;
            int e   = lin >> 4;
            int c4  = lin & 15;
            const float* src = w + (size_t)e * D_DIM + k0 + c4 * 4;
            int sw = c4 ^ (e & 7);
            uint32_t dst = (uint32_t)__cvta_generic_to_shared(&Wb[e * KC + sw * 4]);
            asm volatile("cp.async.cg.shared.global [%0], [%1], 16;\n" :: "r"(dst), "l"(src));
        }
        asm volatile("cp.async.commit_group;\n");
    };

    // ---- mainloop ----------------------------------------------------------
    ull acc[2][4];
    #pragma unroll
    for (int r = 0; r < 2; ++r)
        #pragma unroll
        for (int j = 0; j < 4; ++j) acc[r][j] = 0ULL;

    load_chunk(0, 0);
    load_chunk(1, 1);

    for (int c = 0; c < NC; ++c) {
        const int buf = c % NBUF;
        if (c == NC - 1) { asm volatile("cp.async.wait_group 0;\n"); }
        else             { asm volatile("cp.async.wait_group 1;\n"); }
        __syncthreads();                              // single barrier per chunk
        if (c + 2 < NC) load_chunk(c + 2, (c + 2) % NBUF);

        const float* Xb = (const float*)(smem + X_OFF(buf));
        const float* Wb = (const float*)(smem + W_OFF(buf));

        // register double-buffered quads: load q+1 while computing q
        float4 xv[2], wv[4], xn[2], wn[4];
        #pragma unroll
        for (int r = 0; r < 2; ++r)
            xv[r] = *reinterpret_cast<const float4*>(&Xb[(rw + r) * XPITCH]);
        #pragma unroll
        for (int j = 0; j < 4; ++j)
            wv[j] = *reinterpret_cast<const float4*>(&Wb[(eh + 8 * j + tx) * KC + (tx << 2)]); // q=0: sw=(0^tx)

        #pragma unroll
        for (int q = 0; q < 16; ++q) {
            if (q < 15) {
                const int qn = q + 1;
                #pragma unroll
                for (int r = 0; r < 2; ++r)
                    xn[r] = *reinterpret_cast<const float4*>(&Xb[(rw + r) * XPITCH + qn * 4]);
                #pragma unroll
                for (int j = 0; j < 4; ++j) {
                    const int e  = eh + 8 * j + tx;
                    const int sw = qn ^ tx;
                    wn[j] = *reinterpret_cast<const float4*>(&Wb[e * KC + sw * 4]);
                }
            }
            #pragma unroll
            for (int r = 0; r < 2; ++r) {
                const ull* px = reinterpret_cast<const ull*>(&xv[r]);
                #pragma unroll
                for (int j = 0; j < 4; ++j) {
                    const ull* pw = reinterpret_cast<const ull*>(&wv[j]);
                    ffma2(acc[r][j], px[0], pw[0]);
                    ffma2(acc[r][j], px[1], pw[1]);
                }
            }
            #pragma unroll
            for (int r = 0; r < 2; ++r) xv[r] = xn[r];
            #pragma unroll
            for (int j = 0; j < 4; ++j) wv[j] = wn[j];
        }
    }
    __syncthreads();   // tiles dead; reuse smem for epilogue

    // ---- epilogue ----------------------------------------------------------
    float* C = (float*)smem;                          // [TILE_M][C_STRIDE]
    #pragma unroll
    for (int r = 0; r < 2; ++r)
        #pragma unroll
        for (int j = 0; j < 4; ++j) {
            float2 f = *reinterpret_cast<float2*>(&acc[r][j]);
            C[(rw + r) * C_STRIDE + (eh + 8 * j + tx)] = f.x + f.y;
        }
    __syncthreads();

    // sigmoid + coalesced scores store
    for (int idx = tid; idx < TILE_M * NEXP; idx += THREADS) {
        const int r = idx >> 6, e = idx & 63;
        const float v = 1.0f / (1.0f + __expf(-C[r * C_STRIDE + e]));
        C[r * C_STRIDE + e] = v;
        if (out_s) out_s[(size_t)row_base * NEXP + idx] = v;
    }
    __syncthreads();

    // per-row top-2 (strict > keeps lowest index on ties, like lax.top_k)
    if (tid < TILE_M) {
        const int r = tid;
        float b0 = -1e30f, b1 = -1e30f;
        int   i0 = 0,      i1 = 0;
        #pragma unroll
        for (int e = 0; e < NEXP; ++e) {
            const float v = C[r * C_STRIDE + e] + bias[e];
            if (v > b0)      { b1 = b0; i1 = i0; b0 = v; i0 = e; }
            else if (v > b1) { b1 = v;  i1 = e; }
        }
        const float w0 = C[r * C_STRIDE + i0];
        const float w1 = C[r * C_STRIDE + i1];
        const float inv = 1.0f / (w0 + w1);
        const int row = row_base + r;
        if (out_w) {
            out_w[row * 2 + 0] = w0 * inv;
            out_w[row * 2 + 1] = w1 * inv;
        }
        if (out_i) {
            out_i[row * 2 + 0] = (float)i0;
            out_i[row * 2 + 1] = (float)i1;
        }
    }
}

extern "C" void kernel_launch(void* const* d_in, const int* in_sizes, int n_in,
                              void* d_out, int out_size) {
    const float* x = (const float*)d_in[0];
    const float* w = (const float*)d_in[1];
    const float* b = (const float*)d_in[2];
    const int N = in_sizes[0] / D_DIM;         // 8192

    float* out = (float*)d_out;
    float* ow = nullptr; float* oi = nullptr; float* os = nullptr;
    if (out_size >= N * (2 * 2 + NEXP)) {      // full concat [w | i | s]
        ow = out; oi = out + (size_t)N * 2; os = out + (size_t)N * 4;
    } else if (out_size == N * NEXP) {
        os = out;
    } else if (out_size == N * 4) {
        ow = out; oi = out + (size_t)N * 2;
    } else {
        ow = out;
    }

    cudaFuncSetAttribute(gate_kernel, cudaFuncAttributeMaxDynamicSharedMemorySize, SMEM_TOTAL);
    gate_kernel<<<N / TILE_M, THREADS, SMEM_TOTAL>>>(x, w, b, ow, oi, os);
}

// round 11
// speedup vs baseline: 1.4896x; 1.4896x over previous
#include <cuda_runtime.h>
#include <cstdint>

// Gate_60421599920823 : MoE sigmoid gating via mma.sync tf32 2-way split.
//   logits = x[8192,4096] @ W^T[4096,64]  (fp32-equivalent: hh+hl+lh tf32 products)
//   scores = sigmoid(logits); top-2 on (scores + bias); weights normalized.
// fp32-FFMA path measured at its pipe floor (~131us); tcgen05 needs sm_103a which
// the harness doesn't target; mma.sync (HMMA) is base-ISA -> tensor pipe via tf32.
// Output: [weights N*2 | indices-as-float N*2 | scores N*64]

#define D_DIM    4096
#define NEXP     64
#define TILE_M   64
#define KC       64
#define NC       (D_DIM / KC)      // 64
#define THREADS  256
#define NBUF     3
#define PITCH    68                // floats per tile row (272B; bank = r*4+c mod 32)

#define X_STAGE_BYTES  (TILE_M * PITCH * 4)         // 17408
#define W_STAGE_BYTES  (NEXP * PITCH * 4)           // 17408
#define X_OFF(b)       ((b) * X_STAGE_BYTES)
#define W_OFF(b)       (NBUF * X_STAGE_BYTES + (b) * W_STAGE_BYTES)
#define SMEM_TOTAL     (NBUF * (X_STAGE_BYTES + W_STAGE_BYTES))   // 104448
#define C_STRIDE       68

__device__ __forceinline__ uint32_t f2tf(float x) {
    uint32_t r;
    asm("cvt.rna.tf32.f32 %0, %1;" : "=r"(r) : "f"(x));
    return r;
}
// split x into tf32 head/tail: x ~= h + l with |err| ~ 2^-22 |x|
__device__ __forceinline__ void tfsplit(float x, uint32_t& h, uint32_t& l) {
    h = f2tf(x);
    l = f2tf(x - __uint_as_float(h));
}
__device__ __forceinline__ void mma_tf32(float* d, const uint32_t* a, const uint32_t* b) {
    asm("mma.sync.aligned.m16n8k8.row.col.f32.tf32.tf32.f32 "
        "{%0,%1,%2,%3}, {%4,%5,%6,%7}, {%8,%9}, {%0,%1,%2,%3};"
        : "+f"(d[0]), "+f"(d[1]), "+f"(d[2]), "+f"(d[3])
        : "r"(a[0]), "r"(a[1]), "r"(a[2]), "r"(a[3]), "r"(b[0]), "r"(b[1]));
}

__global__ __launch_bounds__(THREADS, 1)
void gate_kernel(const float* __restrict__ x,
                 const float* __restrict__ w,
                 const float* __restrict__ bias,
                 float* __restrict__ out_w,
                 float* __restrict__ out_i,
                 float* __restrict__ out_s)
{
    extern __shared__ char smem[];
    const int tid = threadIdx.x;
    const int row_base = blockIdx.x * TILE_M;

    const int lane = tid & 31;
    const int wid  = tid >> 5;         // 0..7
    const int wm   = wid & 3;          // m-tile: rows wm*16 .. wm*16+15
    const int wn   = wid >> 2;         // expert half: wn*32 .. wn*32+31
    const int g    = lane >> 2;        // group id 0..7
    const int q    = lane & 3;         // thread-in-group 0..3

    // ---- async chunk loader (4 X-float4 + 4 W-float4 per thread) ----------
    auto load_chunk = [&](int c, int buf) {
        const int k0 = c * KC;
        float* Xb = (float*)(smem + X_OFF(buf));
        float* Wb = (float*)(smem + W_OFF(buf));
        #pragma unroll
        for (int i = 0; i < 4; ++i) {                 // X: 64 rows x 16 float4
            int lin = tid + i * THREADS;              // 0..1023
            int r   = lin >> 4;
            int c4  = lin & 15;
            const float* src = x + (size_t)(row_base + r) * D_DIM + k0 + c4 * 4;
            uint32_t dst = (uint32_t)__cvta_generic_to_shared(&Xb[r * PITCH + c4 * 4]);
            asm volatile("cp.async.cg.shared.global [%0], [%1], 16;\n" :: "r"(dst), "l"(src));
        }
        #pragma unroll
        for (int i = 0; i < 4; ++i) {                 // W: 64 experts x 16 float4
            int lin = tid + i * THREADS;
            int e   = lin >> 4;
            int c4  = lin & 15;
            const float* src = w + (size_t)e * D_DIM + k0 + c4 * 4;
            uint32_t dst = (uint32_t)__cvta_generic_to_shared(&Wb[e * PITCH + c4 * 4]);
            asm volatile("cp.async.cg.shared.global [%0], [%1], 16;\n" :: "r"(dst), "l"(src));
        }
        asm volatile("cp.async.commit_group;\n");
    };

    // ---- mainloop ----------------------------------------------------------
    float d[4][4];
    #pragma unroll
    for (int nt = 0; nt < 4; ++nt)
        #pragma unroll
        for (int i = 0; i < 4; ++i) d[nt][i] = 0.0f;

    load_chunk(0, 0);
    load_chunk(1, 1);

    const int ar0 = wm * 16 + g;       // A fragment rows ar0, ar0+8

    for (int c = 0; c < NC; ++c) {
        const int buf = c % NBUF;
        if (c == NC - 1) { asm volatile("cp.async.wait_group 0;\n"); }
        else             { asm volatile("cp.async.wait_group 1;\n"); }
        __syncthreads();                              // single barrier per chunk
        if (c + 2 < NC) load_chunk(c + 2, (c + 2) % NBUF);

        const float* Xb = (const float*)(smem + X_OFF(buf));
        const float* Wb = (const float*)(smem + W_OFF(buf));

        #pragma unroll
        for (int ks = 0; ks < KC / 8; ++ks) {         // 8 k-steps of k=8
            const int k0 = ks * 8;
            // A fragment (m16 x k8, row-major): 4 conflict-free LDS.32
            const float a0 = Xb[ar0 * PITCH + k0 + q];
            const float a1 = Xb[(ar0 + 8) * PITCH + k0 + q];
            const float a2 = Xb[ar0 * PITCH + k0 + q + 4];
            const float a3 = Xb[(ar0 + 8) * PITCH + k0 + q + 4];
            uint32_t Ah[4], Al[4];
            tfsplit(a0, Ah[0], Al[0]);
            tfsplit(a1, Ah[1], Al[1]);
            tfsplit(a2, Ah[2], Al[2]);
            tfsplit(a3, Ah[3], Al[3]);

            #pragma unroll
            for (int nt = 0; nt < 4; ++nt) {
                const int e0 = wn * 32 + nt * 8;
                // B fragment (k8 x n8, col-major): B[k][n] = W[e0+n][k]
                const float b0 = Wb[(e0 + g) * PITCH + k0 + q];
                const float b1 = Wb[(e0 + g) * PITCH + k0 + q + 4];
                uint32_t Bh[2], Bl[2];
                tfsplit(b0, Bh[0], Bl[0]);
                tfsplit(b1, Bh[1], Bl[1]);
                mma_tf32(d[nt], Ah, Bh);   // hh
                mma_tf32(d[nt], Ah, Bl);   // hl
                mma_tf32(d[nt], Al, Bh);   // lh
            }
        }
    }
    __syncthreads();   // tiles dead; reuse smem for epilogue

    // ---- epilogue: accumulators -> smem ------------------------------------
    float* C = (float*)smem;                          // [TILE_M][C_STRIDE]
    #pragma unroll
    for (int nt = 0; nt < 4; ++nt) {
        const int cb = wn * 32 + nt * 8 + q * 2;
        C[ar0 * C_STRIDE + cb + 0]       = d[nt][0];
        C[ar0 * C_STRIDE + cb + 1]       = d[nt][1];
        C[(ar0 + 8) * C_STRIDE + cb + 0] = d[nt][2];
        C[(ar0 + 8) * C_STRIDE + cb + 1] = d[nt][3];
    }
    __syncthreads();

    // sigmoid + coalesced scores store
    for (int idx = tid; idx < TILE_M * NEXP; idx += THREADS) {
        const int r = idx >> 6, e = idx & 63;
        const float v = 1.0f / (1.0f + __expf(-C[r * C_STRIDE + e]));
        C[r * C_STRIDE + e] = v;
        if (out_s) out_s[(size_t)row_base * NEXP + idx] = v;
    }
    __syncthreads();

    // per-row top-2 (strict > keeps lowest index on ties, like lax.top_k)
    if (tid < TILE_M) {
        const int r = tid;
        float b0 = -1e30f, b1 = -1e30f;
        int   i0 = 0,      i1 = 0;
        #pragma unroll
        for (int e = 0; e < NEXP; ++e) {
            const float v = C[r * C_STRIDE + e] + bias[e];
            if (v > b0)      { b1 = b0; i1 = i0; b0 = v; i0 = e; }
            else if (v > b1) { b1 = v;  i1 = e; }
        }
        const float w0 = C[r * C_STRIDE + i0];
        const float w1 = C[r * C_STRIDE + i1];
        const float inv = 1.0f / (w0 + w1);
        const int row = row_base + r;
        if (out_w) {
            out_w[row * 2 + 0] = w0 * inv;
            out_w[row * 2 + 1] = w1 * inv;
        }
        if (out_i) {
            out_i[row * 2 + 0] = (float)i0;
            out_i[row * 2 + 1] = (float)i1;
        }
    }
}

extern "C" void kernel_launch(void* const* d_in, const int* in_sizes, int n_in,
                              void* d_out, int out_size) {
    const float* x = (const float*)d_in[0];
    const float* w = (const float*)d_in[1];
    const float* b = (const float*)d_in[2];
    const int N = in_sizes[0] / D_DIM;         // 8192

    float* out = (float*)d_out;
    float* ow = nullptr; float* oi = nullptr; float* os = nullptr;
    if (out_size >= N * (2 * 2 + NEXP)) {      // full concat [w | i | s]
        ow = out; oi = out + (size_t)N * 2; os = out + (size_t)N * 4;
    } else if (out_size == N * NEXP) {
        os = out;
    } else if (out_size == N * 4) {
        ow = out; oi = out + (size_t)N * 2;
    } else {
        ow = out;
    }

    cudaFuncSetAttribute(gate_kernel, cudaFuncAttributeMaxDynamicSharedMemorySize, SMEM_TOTAL);
    gate_kernel<<<N / TILE_M, THREADS, SMEM_TOTAL>>>(x, w, b, ow, oi, os);
}

// round 13
// speedup vs baseline: 2.5496x; 1.7116x over previous
#include <cuda_runtime.h>
#include <cstdint>

// Gate_60421599920823 : MoE sigmoid gating via mma.sync bf16 2-way split.
//   logits = x[8192,4096] @ W^T[4096,64]  (fp32-equivalent: hh+hl+lh bf16 products,
//   split ONCE at load time into interleaved (h,l) smem tiles)
//   scores = sigmoid(logits); top-2 on (scores + bias); weights normalized.
// tf32 3-term path validated round 11 (127us, tensor 34%, alu 36% = split overhead).
// This round: k16 bf16 halves HMMA count; load-time split removes inner-loop cvt.
// Output: [weights N*2 | indices-as-float N*2 | scores N*64]

#define D_DIM    4096
#define NEXP     64
#define TILE_M   64
#define KC       64
#define NC       (D_DIM / KC)      // 64
#define THREADS  256
#define PITCHU   72                // u32 per packed row (64 data + 8 pad)
#define TILE_U32 (64 * PITCHU)     // 4608 u32 per tile (X or W)
#define BUF_U32  (2 * TILE_U32)    // X + W per stage
#define SMEM_TOTAL (2 * BUF_U32 * 4)   // 73728 B
#define C_STRIDE 68

// pack two floats' bf16 heads (f0 -> low half) and tails
__device__ __forceinline__ void split2(float f0, float f1, uint32_t& h, uint32_t& l) {
    asm("cvt.rn.bf16x2.f32 %0, %1, %2;" : "=r"(h) : "f"(f1), "f"(f0));
    float r0 = f0 - __uint_as_float(h << 16);
    float r1 = f1 - __uint_as_float(h & 0xFFFF0000u);
    asm("cvt.rn.bf16x2.f32 %0, %1, %2;" : "=r"(l) : "f"(r1), "f"(r0));
}
__device__ __forceinline__ void mma_bf16(float* d, const uint32_t* a, const uint32_t* b) {
    asm("mma.sync.aligned.m16n8k16.row.col.f32.bf16.bf16.f32 "
        "{%0,%1,%2,%3}, {%4,%5,%6,%7}, {%8,%9}, {%0,%1,%2,%3};"
        : "+f"(d[0]), "+f"(d[1]), "+f"(d[2]), "+f"(d[3])
        : "r"(a[0]), "r"(a[1]), "r"(a[2]), "r"(a[3]), "r"(b[0]), "r"(b[1]));
}

__global__ __launch_bounds__(THREADS, 1)
void gate_kernel(const float* __restrict__ x,
                 const float* __restrict__ w,
                 const float* __restrict__ bias,
                 float* __restrict__ out_w,
                 float* __restrict__ out_i,
                 float* __restrict__ out_s)
{
    extern __shared__ char smem[];
    uint32_t* Sp = (uint32_t*)smem;
    const int tid = threadIdx.x;
    const int row_base = blockIdx.x * TILE_M;

    const int lane = tid & 31;
    const int wid  = tid >> 5;         // 0..7
    const int wm   = wid & 3;          // m-tile: rows wm*16 .. +15
    const int wn   = wid >> 2;         // expert half
    const int g    = lane >> 2;        // 0..7
    const int q    = lane & 3;         // 0..3
    const int ar0  = wm * 16 + g;

    // per-thread gmem staging: 4 X float4 + 4 W float4 per chunk
    float4 xr[4], wr[4];
    int rr[4], cc[4];
    #pragma unroll
    for (int i = 0; i < 4; ++i) { int lin = tid + i * THREADS; rr[i] = lin >> 4; cc[i] = lin & 15; }

    auto load_gmem = [&](int c) {
        const int k0 = c * KC;
        #pragma unroll
        for (int i = 0; i < 4; ++i) {
            xr[i] = *(const float4*)(x + (size_t)(row_base + rr[i]) * D_DIM + k0 + cc[i] * 4);
            wr[i] = *(const float4*)(w + (size_t)rr[i] * D_DIM + k0 + cc[i] * 4);
        }
    };
    // split fp32 -> interleaved (h,l) bf16x2 pairs; one STS.128 per float4
    auto split_store = [&](int buf) {
        uint32_t* Xp = Sp + buf * BUF_U32;
        uint32_t* Wp = Xp + TILE_U32;
        #pragma unroll
        for (int i = 0; i < 4; ++i) {
            uint32_t h0, l0, h1, l1;
            split2(xr[i].x, xr[i].y, h0, l0);
            split2(xr[i].z, xr[i].w, h1, l1);
            *(uint4*)&Xp[rr[i] * PITCHU + cc[i] * 4] = make_uint4(h0, l0, h1, l1);
            split2(wr[i].x, wr[i].y, h0, l0);
            split2(wr[i].z, wr[i].w, h1, l1);
            *(uint4*)&Wp[rr[i] * PITCHU + cc[i] * 4] = make_uint4(h0, l0, h1, l1);
        }
    };

    // ---- mainloop ----------------------------------------------------------
    float d[4][4];
    #pragma unroll
    for (int nt = 0; nt < 4; ++nt)
        #pragma unroll
        for (int i = 0; i < 4; ++i) d[nt][i] = 0.0f;

    load_gmem(0);
    split_store(0);
    load_gmem(1);
    __syncthreads();

    for (int c = 0; c < NC; ++c) {
        const uint32_t* Xp = Sp + (c & 1) * BUF_U32;
        const uint32_t* Wp = Xp + TILE_U32;

        #pragma unroll
        for (int ks = 0; ks < KC / 16; ++ks) {        // 4 k-steps of k=16
            const int ko = 16 * ks + 2 * q;           // u32 index of (h,l) pair
            const uint2 a0 = *(const uint2*)&Xp[ar0 * PITCHU + ko];
            const uint2 a1 = *(const uint2*)&Xp[(ar0 + 8) * PITCHU + ko];
            const uint2 a2 = *(const uint2*)&Xp[ar0 * PITCHU + ko + 8];
            const uint2 a3 = *(const uint2*)&Xp[(ar0 + 8) * PITCHU + ko + 8];
            const uint32_t Ah[4] = {a0.x, a1.x, a2.x, a3.x};
            const uint32_t Al[4] = {a0.y, a1.y, a2.y, a3.y};
            #pragma unroll
            for (int nt = 0; nt < 4; ++nt) {
                const int er = (wn * 32 + nt * 8 + g) * PITCHU + ko;
                const uint2 b0 = *(const uint2*)&Wp[er];
                const uint2 b1 = *(const uint2*)&Wp[er + 8];
                const uint32_t Bh[2] = {b0.x, b1.x};
                const uint32_t Bl[2] = {b0.y, b1.y};
                mma_bf16(d[nt], Ah, Bh);   // hh
                mma_bf16(d[nt], Ah, Bl);   // hl
                mma_bf16(d[nt], Al, Bh);   // lh
            }
        }
        __syncthreads();
        if (c + 1 < NC) {
            split_store((c + 1) & 1);                 // other buffer; regs hold chunk c+1
            if (c + 2 < NC) load_gmem(c + 2);
            __syncthreads();
        }
    }

    // ---- epilogue: accumulators -> smem ------------------------------------
    __syncthreads();
    float* C = (float*)smem;                          // [TILE_M][C_STRIDE]
    #pragma unroll
    for (int nt = 0; nt < 4; ++nt) {
        const int cb = wn * 32 + nt * 8 + q * 2;
        C[ar0 * C_STRIDE + cb + 0]       = d[nt][0];
        C[ar0 * C_STRIDE + cb + 1]       = d[nt][1];
        C[(ar0 + 8) * C_STRIDE + cb + 0] = d[nt][2];
        C[(ar0 + 8) * C_STRIDE + cb + 1] = d[nt][3];
    }
    __syncthreads();

    // sigmoid + coalesced scores store
    for (int idx = tid; idx < TILE_M * NEXP; idx += THREADS) {
        const int r = idx >> 6, e = idx & 63;
        const float v = 1.0f / (1.0f + __expf(-C[r * C_STRIDE + e]));
        C[r * C_STRIDE + e] = v;
        if (out_s) out_s[(size_t)row_base * NEXP + idx] = v;
    }
    __syncthreads();

    // per-row top-2 (strict > keeps lowest index on ties, like lax.top_k)
    if (tid < TILE_M) {
        const int r = tid;
        float b0 = -1e30f, b1 = -1e30f;
        int   i0 = 0,      i1 = 0;
        #pragma unroll
        for (int e = 0; e < NEXP; ++e) {
            const float v = C[r * C_STRIDE + e] + bias[e];
            if (v > b0)      { b1 = b0; i1 = i0; b0 = v; i0 = e; }
            else if (v > b1) { b1 = v;  i1 = e; }
        }
        const float w0 = C[r * C_STRIDE + i0];
        const float w1 = C[r * C_STRIDE + i1];
        const float inv = 1.0f / (w0 + w1);
        const int row = row_base + r;
        if (out_w) {
            out_w[row * 2 + 0] = w0 * inv;
            out_w[row * 2 + 1] = w1 * inv;
        }
        if (out_i) {
            out_i[row * 2 + 0] = (float)i0;
            out_i[row * 2 + 1] = (float)i1;
        }
    }
}

extern "C" void kernel_launch(void* const* d_in, const int* in_sizes, int n_in,
                              void* d_out, int out_size) {
    const float* x = (const float*)d_in[0];
    const float* w = (const float*)d_in[1];
    const float* b = (const float*)d_in[2];
    const int N = in_sizes[0] / D_DIM;         // 8192

    float* out = (float*)d_out;
    float* ow = nullptr; float* oi = nullptr; float* os = nullptr;
    if (out_size >= N * (2 * 2 + NEXP)) {      // full concat [w | i | s]
        ow = out; oi = out + (size_t)N * 2; os = out + (size_t)N * 4;
    } else if (out_size == N * NEXP) {
        os = out;
    } else if (out_size == N * 4) {
        ow = out; oi = out + (size_t)N * 2;
    } else {
        ow = out;
    }

    cudaFuncSetAttribute(gate_kernel, cudaFuncAttributeMaxDynamicSharedMemorySize, SMEM_TOTAL);
    gate_kernel<<<N / TILE_M, THREADS, SMEM_TOTAL>>>(x, w, b, ow, oi, os);
}